// round 10
// baseline (speedup 1.0000x reference)
#include <cuda_runtime.h>
#include <cstdint>

#define GENES 2048
#define HEADS 8
#define BATCH 16
#define NP 6           // Taylor powers 0..5 (|s|<~0.12 -> err < 2e-9)
#define TPB  256
#define NVAL 11        // A1..A5, B0..B5  (A0 = 2048 exact)

__constant__ float c_invfact[NP] = {
    1.0f, 1.0f, 0.5f, 1.0f / 6.0f, 1.0f / 24.0f, 1.0f / 120.0f
};

// ---------------- packed f32x2 helpers ----------------
__device__ __forceinline__ unsigned long long pk2(float lo, float hi) {
    unsigned long long r;
    asm("mov.b64 %0, {%1, %2};" : "=l"(r) : "f"(lo), "f"(hi));
    return r;
}
__device__ __forceinline__ void upk2(float& lo, float& hi, unsigned long long v) {
    asm("mov.b64 {%0, %1}, %2;" : "=f"(lo), "=f"(hi) : "l"(v));
}
__device__ __forceinline__ unsigned long long mul2(unsigned long long a, unsigned long long b) {
    unsigned long long r;
    asm("mul.rn.f32x2 %0, %1, %2;" : "=l"(r) : "l"(a), "l"(b));
    return r;
}
__device__ __forceinline__ unsigned long long add2(unsigned long long a, unsigned long long b) {
    unsigned long long r;
    asm("add.rn.f32x2 %0, %1, %2;" : "=l"(r) : "l"(a), "l"(b));
    return r;
}
__device__ __forceinline__ unsigned long long fma2(unsigned long long a, unsigned long long b,
                                                   unsigned long long c) {
    unsigned long long r;
    asm("fma.rn.f32x2 %0, %1, %2, %3;" : "=l"(r) : "l"(a), "l"(b), "l"(c));
    return r;
}

// ---------------------------------------------------------------------------
// NO clusters, NO DSMEM, NO cross-CTA sync. 128 independent CTAs.
// CTA (b, slice): warp w REDUNDANTLY computes head w's moments over ALL 2048
// genes of batch b (64 genes/lane, packed f32x2), butterfly-reduces 11 values,
// stages them in smem. One __syncthreads. Phase 2: thread t computes output
// gene (slice*256 + t) via packed 8-head Horner + exact-exp diagonal fixup.
// Redundancy costs ~2.2k cyc of FMA (pipe was 5% busy); removes the ~6k-cycle
// cluster-launch/barrier/fan-out tax the last 4 rounds could not shrink.
// ---------------------------------------------------------------------------
__global__ void __launch_bounds__(TPB, 1)
fused_attn_kernel(const float* __restrict__ x,
                  const float* __restrict__ WQ,
                  const float* __restrict__ WK,
                  const float* __restrict__ WV,
                  const float* __restrict__ W0,
                  float* __restrict__ out)
{
    const int b     = blockIdx.x >> 3;      // batch
    const int slice = blockIdx.x & 7;       // 256-gene output slice
    const int tid   = threadIdx.x;
    const int w     = tid >> 5;             // warp = head for phase 1
    const int lane  = tid & 31;

    __shared__ __align__(8) float sMomA[NP - 1][HEADS];   // A1..A5 per head
    __shared__ __align__(8) float sMomB[NP][HEADS];       // B0..B5 per head
    __shared__ float sW0[HEADS];

    const float* __restrict__ xb = x + b * GENES;

    // -------- Prefetch phase-2 operands (overlap with phase-1 epoch) --------
    const int g = slice * 256 + tid;
    const float xg = xb[g];
    float pq[HEADS], pkk[HEADS], pv[HEADS];
#pragma unroll
    for (int hh = 0; hh < HEADS; hh++) {
        pq[hh]  = WQ[hh * GENES + g];
        pkk[hh] = WK[hh * GENES + g];
        pv[hh]  = WV[hh * GENES + g];
    }
    if (tid < HEADS) sW0[tid] = W0[tid];

    // -------- Phase 1: warp w = head w, full 2048-gene moment sweep --------
    const float4* __restrict__ x4  = (const float4*)xb;
    const float4* __restrict__ wk4 = (const float4*)(WK + w * GENES);
    const float4* __restrict__ wv4 = (const float4*)(WV + w * GENES);

    unsigned long long A[NP - 1], Bm[NP];
#pragma unroll
    for (int n = 0; n < NP - 1; n++) A[n] = 0ull;
#pragma unroll
    for (int n = 0; n < NP; n++) Bm[n] = 0ull;

    // 2048 floats / 32 lanes = 16 float4 per lane; unroll 4 for MLP vs regs
#pragma unroll 4
    for (int c = 0; c < GENES / (4 * 32); c++) {          // 16 chunks
        const int i = c * 32 + lane;                      // coalesced
        const float4 xv = x4[i];
        const float4 kv = wk4[i];
        const float4 vv = wv4[i];

        const unsigned long long xp0 = pk2(xv.x, xv.y);
        const unsigned long long xp1 = pk2(xv.z, xv.w);
        const unsigned long long k0  = mul2(xp0, pk2(kv.x, kv.y));
        const unsigned long long k1  = mul2(xp1, pk2(kv.z, kv.w));
        const unsigned long long v0  = mul2(xp0, pk2(vv.x, vv.y));
        const unsigned long long v1  = mul2(xp1, pk2(vv.z, vv.w));

        Bm[0] = add2(Bm[0], v0);
        Bm[0] = add2(Bm[0], v1);
        unsigned long long p0 = k0, p1 = k1;
#pragma unroll
        for (int n = 1; n < NP; n++) {
            A[n - 1] = add2(A[n - 1], p0);
            A[n - 1] = add2(A[n - 1], p1);
            Bm[n]    = fma2(p0, v0, Bm[n]);
            Bm[n]    = fma2(p1, v1, Bm[n]);
            if (n < NP - 1) { p0 = mul2(p0, k0); p1 = mul2(p1, k1); }
        }
    }

    // -------- Exp-diagonal terms: MUFU latency hides under SHFLs below ------
    float qs[HEADS], ev[HEADS];
#pragma unroll
    for (int hh = 0; hh < HEADS; hh++) {
        qs[hh] = xg * pq[hh];
        ev[hh] = __expf(qs[hh] * (xg * pkk[hh])) * (xg * pv[hh]);
    }

    // -------- SHFL-butterfly warp reduce (11 scalars) --------
    float vals[NVAL];
#pragma unroll
    for (int n = 0; n < NP - 1; n++) {
        float lo, hi; upk2(lo, hi, A[n]);
        vals[n] = lo + hi;
    }
#pragma unroll
    for (int n = 0; n < NP; n++) {
        float lo, hi; upk2(lo, hi, Bm[n]);
        vals[NP - 1 + n] = lo + hi;
    }
#pragma unroll
    for (int i = 0; i < NVAL; i++) {
#pragma unroll
        for (int off = 16; off > 0; off >>= 1)
            vals[i] += __shfl_xor_sync(0xFFFFFFFFu, vals[i], off);
    }

    // Lanes 0..10 each own one reduced value: scale + store to smem (head w)
    if (lane < NVAL) {
        // gather my value from the butterfly result held by every lane:
        // all lanes have the full sums, so lane L just picks vals[L].
        float s;
        switch (lane) {                     // fully unrolled reg-indexed pick
            case 0:  s = vals[0];  break;
            case 1:  s = vals[1];  break;
            case 2:  s = vals[2];  break;
            case 3:  s = vals[3];  break;
            case 4:  s = vals[4];  break;
            case 5:  s = vals[5];  break;
            case 6:  s = vals[6];  break;
            case 7:  s = vals[7];  break;
            case 8:  s = vals[8];  break;
            case 9:  s = vals[9];  break;
            default: s = vals[10]; break;
        }
        if (lane < NP - 1)
            sMomA[lane][w] = s * c_invfact[lane + 1];            // A_{lane+1}
        else
            sMomB[lane - (NP - 1)][w] = s * c_invfact[lane - (NP - 1)]; // B_n
    }
    __syncthreads();          // the ONLY synchronization in the kernel

    // -------- Phase 2: packed head-pair Horner (smem broadcast reads) -------
    const unsigned long long a0_2 = pk2(2048.0f, 2048.0f);       // A0/0! exact
    float acc = 0.0f;

#pragma unroll
    for (int p = 0; p < HEADS / 2; p++) {
        const int h0 = 2 * p;
        const unsigned long long q2 = pk2(qs[h0], qs[h0 + 1]);

        unsigned long long P0 = *(const unsigned long long*)&sMomA[NP - 2][h0];
#pragma unroll
        for (int n = NP - 3; n >= 0; n--)
            P0 = fma2(P0, q2, *(const unsigned long long*)&sMomA[n][h0]);
        P0 = fma2(P0, q2, a0_2);

        unsigned long long P1 = *(const unsigned long long*)&sMomB[NP - 1][h0];
#pragma unroll
        for (int n = NP - 2; n >= 0; n--)
            P1 = fma2(P1, q2, *(const unsigned long long*)&sMomB[n][h0]);

        float P0a, P0b, P1a, P1b;
        upk2(P0a, P0b, P0);
        upk2(P1a, P1b, P1);

        const float z0 = __fdividef(P1a - ev[h0],     P0a);
        const float z1 = __fdividef(P1b - ev[h0 + 1], P0b);
        acc = fmaf(z0, sW0[h0],     acc);
        acc = fmaf(z1, sW0[h0 + 1], acc);
    }

    out[b * GENES + g] = acc;
}

// ---------------------------------------------------------------------------
extern "C" void kernel_launch(void* const* d_in, const int* in_sizes, int n_in,
                              void* d_out, int out_size)
{
    const float* x  = (const float*)d_in[0];
    const float* WQ = (const float*)d_in[1];
    const float* WK = (const float*)d_in[2];
    const float* WV = (const float*)d_in[3];
    const float* W0 = (const float*)d_in[4];
    float* out = (float*)d_out;

    fused_attn_kernel<<<BATCH * HEADS, TPB>>>(x, WQ, WK, WV, W0, out);
}